// round 12
// baseline (speedup 1.0000x reference)
#include <cuda_runtime.h>

#define KNBR 16
#define F_IN 7
#define F_HID 40
#define F_OUT 3
#define HP (F_HID / 2)      // 20 hidden pairs
#define BLOCK 128

// Packed weight image in GLOBAL memory (L1-hot, warp-uniform __ldg reads).
//   W1[0..279]  row-major f*40+h
//   b1[280..319]
//   W2P[320..439]  packed h-pair layout, pre-scaled by 1/K
//   b2[440..442]
#define OFF_W1 0
#define OFF_B1 280
#define OFF_W2P 320
#define OFF_B2 440
#define W_TOTAL 444

typedef unsigned long long u64;

__device__ __align__(16) float g_stage[W_TOTAL];

// ---- f32x2 packed helpers (sm_103a) ----
__device__ __forceinline__ u64 pack2(float lo, float hi) {
    u64 r;
    asm("mov.b64 %0, {%1, %2};" : "=l"(r) : "f"(lo), "f"(hi));
    return r;
}
__device__ __forceinline__ u64 fma2(u64 a, u64 b, u64 c) {
    u64 d;
    asm("fma.rn.f32x2 %0, %1, %2, %3;" : "=l"(d) : "l"(a), "l"(b), "l"(c));
    return d;
}
__device__ __forceinline__ u64 add2(u64 a, u64 b) {
    u64 d;
    asm("add.rn.f32x2 %0, %1, %2;" : "=l"(d) : "l"(a), "l"(b));
    return d;
}
__device__ __forceinline__ void unpack2(u64 v, float& lo, float& hi) {
    asm("mov.b64 {%0, %1}, %2;" : "=f"(lo), "=f"(hi) : "l"(v));
}
__device__ __forceinline__ u64 relu2(u64 v) {
    float lo, hi;
    unpack2(v, lo, hi);
    return pack2(fmaxf(lo, 0.f), fmaxf(hi, 0.f));   // FMNMX on alu pipe
}
__device__ __forceinline__ u64 f4lo(const float4& v) { return pack2(v.x, v.y); }
__device__ __forceinline__ u64 f4hi(const float4& v) { return pack2(v.z, v.w); }

// Pack all weights into one contiguous staging buffer (1 graph node).
__global__ void gather_weights(const float* __restrict__ W1,
                               const float* __restrict__ b1,
                               const float* __restrict__ W2,
                               const float* __restrict__ b2) {
    int i = threadIdx.x;
    if (i < 280)      g_stage[OFF_W1 + i]       = W1[i];
    else if (i < 320) g_stage[OFF_B1 + i - 280] = b1[i - 280];
    else if (i < 440) {
        int j = i - 320;                 // packed W2P index
        int p = j / 6, s = j % 6;        // pair p, slot s
        int o = s >> 1;                  // output index
        int h = 2 * p + (s & 1);         // which h of the pair
        g_stage[OFF_W2P + j] = W2[h * F_OUT + o] * (1.0f / (float)KNBR);
    }
    else if (i < 443) g_stage[OFF_B2 + i - 440] = b2[i - 440];
}

__global__ __launch_bounds__(BLOCK, 8)
void aggre_mlp_kernel(const float* __restrict__ mailbox,
                      float* __restrict__ out,
                      int n_nodes) {
    const int tid = threadIdx.x;
    const long long gt = (long long)blockIdx.x * BLOCK + tid;
    if (gt >= (long long)n_nodes * 4) return;

    const long long node = gt >> 2;          // 4 threads per node
    const int sub = (int)(gt & 3);

    // 4 messages * 7 floats = 7 float4, contiguous & 16B aligned.
    const float4* src = reinterpret_cast<const float4*>(mailbox) + node * 28 + sub * 7;
    // Duplicate each message scalar into both f32x2 halves (operand-a).
    u64 md[28];
    #pragma unroll
    for (int i = 0; i < 7; i++) {
        float4 v = src[i];
        md[4 * i + 0] = pack2(v.x, v.x);
        md[4 * i + 1] = pack2(v.y, v.y);
        md[4 * i + 2] = pack2(v.z, v.z);
        md[4 * i + 3] = pack2(v.w, v.w);
    }

    // Output accumulators, packed over (even h, odd h) of each pair.
    u64 y0p = pack2(0.f, 0.f);
    u64 y1p = pack2(0.f, 0.f);
    u64 y2p = pack2(0.f, 0.f);

    // Warp-uniform weight reads: __ldg LDG.128 from the tiny L1-hot image.
    const float4* gW1q = reinterpret_cast<const float4*>(&g_stage[OFF_W1]);  // stride 10 per f
    const float4* gB1q = reinterpret_cast<const float4*>(&g_stage[OFF_B1]);
    const float4* gW2q = reinterpret_cast<const float4*>(&g_stage[OFF_W2P]);

    // Process 2 h-pairs (4 hidden units) per iteration; wide 128-bit uniform loads.
    #pragma unroll
    for (int j = 0; j < HP / 2; j++) {       // j-th 4-h block: pairs 2j, 2j+1
        const float4 bq = __ldg(&gB1q[j]);   // b1[4j..4j+3]
        const u64 bpA = f4lo(bq), bpB = f4hi(bq);
        u64 a0 = bpA, a1 = bpA, a2 = bpA, a3 = bpA;   // pair A chains
        u64 c0 = bpB, c1 = bpB, c2 = bpB, c3 = bpB;   // pair B chains
        #pragma unroll
        for (int f = 0; f < F_IN; f++) {
            const float4 wq = __ldg(&gW1q[f * 10 + j]);   // W1[f][4j..4j+3]
            const u64 wA = f4lo(wq), wB = f4hi(wq);
            a0 = fma2(md[f],      wA, a0);  c0 = fma2(md[f],      wB, c0);
            a1 = fma2(md[7  + f], wA, a1);  c1 = fma2(md[7  + f], wB, c1);
            a2 = fma2(md[14 + f], wA, a2);  c2 = fma2(md[14 + f], wB, c2);
            a3 = fma2(md[21 + f], wA, a3);  c3 = fma2(md[21 + f], wB, c3);
        }
        // relu (alu pipe) + packed sum over 4 messages (3 add2 per pair)
        const u64 hsA = add2(add2(relu2(a0), relu2(a1)),
                             add2(relu2(a2), relu2(a3)));
        const u64 hsB = add2(add2(relu2(c0), relu2(c1)),
                             add2(relu2(c2), relu2(c3)));
        // layer 2 folded through mean; packed W2 pairs, 3 uniform 128-bit loads
        const float4 w2q0 = __ldg(&gW2q[3 * j + 0]);  // (A.o0, A.o1)
        const float4 w2q1 = __ldg(&gW2q[3 * j + 1]);  // (A.o2, B.o0)
        const float4 w2q2 = __ldg(&gW2q[3 * j + 2]);  // (B.o1, B.o2)
        y0p = fma2(hsA, f4lo(w2q0), y0p);
        y1p = fma2(hsA, f4hi(w2q0), y1p);
        y2p = fma2(hsA, f4lo(w2q1), y2p);
        y0p = fma2(hsB, f4hi(w2q1), y0p);
        y1p = fma2(hsB, f4lo(w2q2), y1p);
        y2p = fma2(hsB, f4hi(w2q2), y2p);
    }

    float e, o;
    unpack2(y0p, e, o); float y0 = e + o;
    unpack2(y1p, e, o); float y1 = e + o;
    unpack2(y2p, e, o); float y2 = e + o;

    // Reduce over the 4 sibling lanes (adjacent lanes: xor 1, then 2).
    #pragma unroll
    for (int d = 1; d < 4; d <<= 1) {
        y0 += __shfl_xor_sync(0xffffffffu, y0, d);
        y1 += __shfl_xor_sync(0xffffffffu, y1, d);
        y2 += __shfl_xor_sync(0xffffffffu, y2, d);
    }

    if (sub < F_OUT) {
        float v = (sub == 0) ? y0 : (sub == 1) ? y1 : y2;
        out[node * F_OUT + sub] = v + __ldg(&g_stage[OFF_B2 + sub]);
    }
}

extern "C" void kernel_launch(void* const* d_in, const int* in_sizes, int n_in,
                              void* d_out, int out_size) {
    const float* mailbox = (const float*)d_in[0];
    float* out = (float*)d_out;

    // 1) Pack weights into contiguous device staging (kernel node).
    gather_weights<<<1, 512>>>((const float*)d_in[1], (const float*)d_in[2],
                               (const float*)d_in[3], (const float*)d_in[4]);
    // 2) Main kernel reads the staged image directly (no memcpy node).
    const int n_nodes = in_sizes[0] / (KNBR * F_IN);
    const long long total_threads = (long long)n_nodes * 4;
    const int blocks = (int)((total_threads + BLOCK - 1) / BLOCK);

    aggre_mlp_kernel<<<blocks, BLOCK>>>(mailbox, out, n_nodes);
}

// round 14
// speedup vs baseline: 1.6176x; 1.6176x over previous
#include <cuda_runtime.h>

#define KNBR 16
#define F_IN 7
#define F_HID 40
#define F_OUT 3
#define HP (F_HID / 2)      // 20 hidden pairs
#define BLOCK 128

// Combined constant layout (all 16B-aligned blocks):
//   W1[0..279]  row-major f*40+h
//   b1[280..319]
//   W2P[320..439]  packed h-pair layout, pre-scaled by 1/K:
//     for p: 6 floats = (W2[2p][0],W2[2p+1][0], W2[2p][1],W2[2p+1][1], W2[2p][2],W2[2p+1][2])
//   b2[440..442]
#define OFF_W1 0
#define OFF_B1 280
#define OFF_W2P 320
#define OFF_B2 440
#define W_TOTAL 444

typedef unsigned long long u64;

__constant__ __align__(16) float cAll[W_TOTAL];
__device__   __align__(16) float g_stage[W_TOTAL];

// ---- f32x2 packed helpers (sm_103a) ----
__device__ __forceinline__ u64 pack2(float lo, float hi) {
    u64 r;
    asm("mov.b64 %0, {%1, %2};" : "=l"(r) : "f"(lo), "f"(hi));
    return r;
}
__device__ __forceinline__ u64 fma2(u64 a, u64 b, u64 c) {
    u64 d;
    asm("fma.rn.f32x2 %0, %1, %2, %3;" : "=l"(d) : "l"(a), "l"(b), "l"(c));
    return d;
}
__device__ __forceinline__ u64 add2(u64 a, u64 b) {
    u64 d;
    asm("add.rn.f32x2 %0, %1, %2;" : "=l"(d) : "l"(a), "l"(b));
    return d;
}
__device__ __forceinline__ void unpack2(u64 v, float& lo, float& hi) {
    asm("mov.b64 {%0, %1}, %2;" : "=f"(lo), "=f"(hi) : "l"(v));
}
__device__ __forceinline__ u64 relu2(u64 v) {
    float lo, hi;
    unpack2(v, lo, hi);
    return pack2(fmaxf(lo, 0.f), fmaxf(hi, 0.f));   // FMNMX on alu pipe
}
__device__ __forceinline__ u64 f4lo(const float4& v) { return pack2(v.x, v.y); }
__device__ __forceinline__ u64 f4hi(const float4& v) { return pack2(v.z, v.w); }

// Pack all weights into one contiguous staging buffer (1 graph node).
__global__ void gather_weights(const float* __restrict__ W1,
                               const float* __restrict__ b1,
                               const float* __restrict__ W2,
                               const float* __restrict__ b2) {
    int i = threadIdx.x;
    if (i < 280)      g_stage[OFF_W1 + i]       = W1[i];
    else if (i < 320) g_stage[OFF_B1 + i - 280] = b1[i - 280];
    else if (i < 440) {
        int j = i - 320;                 // packed W2P index
        int p = j / 6, s = j % 6;        // pair p, slot s
        int o = s >> 1;                  // output index
        int h = 2 * p + (s & 1);         // which h of the pair
        g_stage[OFF_W2P + j] = W2[h * F_OUT + o] * (1.0f / (float)KNBR);
    }
    else if (i < 443) g_stage[OFF_B2 + i - 440] = b2[i - 440];
}

__global__ __launch_bounds__(BLOCK, 6)
void aggre_mlp_kernel(const float* __restrict__ mailbox,
                      float* __restrict__ out,
                      int n_nodes) {
    const int tid = threadIdx.x;
    const long long gt = (long long)blockIdx.x * BLOCK + tid;
    if (gt >= (long long)n_nodes * 4) return;

    const long long node = gt >> 2;          // 4 threads per node
    const int sub = (int)(gt & 3);

    // 4 messages * 7 floats = 7 float4, contiguous & 16B aligned.
    const float4* src = reinterpret_cast<const float4*>(mailbox) + node * 28 + sub * 7;
    // Duplicate each message scalar into both f32x2 halves (operand-a).
    u64 md[28];
    #pragma unroll
    for (int i = 0; i < 7; i++) {
        float4 v = src[i];
        md[4 * i + 0] = pack2(v.x, v.x);
        md[4 * i + 1] = pack2(v.y, v.y);
        md[4 * i + 2] = pack2(v.z, v.z);
        md[4 * i + 3] = pack2(v.w, v.w);
    }

    // Output accumulators, packed over (even h, odd h) of each pair.
    u64 y0p = pack2(0.f, 0.f);
    u64 y1p = pack2(0.f, 0.f);
    u64 y2p = pack2(0.f, 0.f);

    const float4* cW1q = reinterpret_cast<const float4*>(&cAll[OFF_W1]);  // stride 10 per f
    const float4* cB1q = reinterpret_cast<const float4*>(&cAll[OFF_B1]);
    const float4* cW2q = reinterpret_cast<const float4*>(&cAll[OFF_W2P]);

    // Process 2 h-pairs (4 hidden units) per iteration -> wide LDC.128 const
    // reads (11 per block vs 22 narrow), staying under the const-port floor.
    #pragma unroll
    for (int j = 0; j < HP / 2; j++) {       // j-th 4-h block: pairs 2j, 2j+1
        const float4 bq = cB1q[j];           // b1[4j..4j+3]
        const u64 bpA = f4lo(bq), bpB = f4hi(bq);
        u64 a0 = bpA, a1 = bpA, a2 = bpA, a3 = bpA;   // pair A chains
        u64 c0 = bpB, c1 = bpB, c2 = bpB, c3 = bpB;   // pair B chains
        #pragma unroll
        for (int f = 0; f < F_IN; f++) {
            const float4 wq = cW1q[f * 10 + j];       // W1[f][4j..4j+3]
            const u64 wA = f4lo(wq), wB = f4hi(wq);
            a0 = fma2(md[f],      wA, a0);  c0 = fma2(md[f],      wB, c0);
            a1 = fma2(md[7  + f], wA, a1);  c1 = fma2(md[7  + f], wB, c1);
            a2 = fma2(md[14 + f], wA, a2);  c2 = fma2(md[14 + f], wB, c2);
            a3 = fma2(md[21 + f], wA, a3);  c3 = fma2(md[21 + f], wB, c3);
        }
        // relu (alu pipe) + packed sum over 4 messages (3 add2 per pair)
        const u64 hsA = add2(add2(relu2(a0), relu2(a1)),
                             add2(relu2(a2), relu2(a3)));
        const u64 hsB = add2(add2(relu2(c0), relu2(c1)),
                             add2(relu2(c2), relu2(c3)));
        // layer 2 folded through mean; packed W2 pairs, 3 LDC.128 per block
        const float4 w2q0 = cW2q[3 * j + 0];  // (A.o0, A.o1)
        const float4 w2q1 = cW2q[3 * j + 1];  // (A.o2, B.o0)
        const float4 w2q2 = cW2q[3 * j + 2];  // (B.o1, B.o2)
        y0p = fma2(hsA, f4lo(w2q0), y0p);
        y1p = fma2(hsA, f4hi(w2q0), y1p);
        y2p = fma2(hsA, f4lo(w2q1), y2p);
        y0p = fma2(hsB, f4hi(w2q1), y0p);
        y1p = fma2(hsB, f4lo(w2q2), y1p);
        y2p = fma2(hsB, f4hi(w2q2), y2p);
    }

    float e, o;
    unpack2(y0p, e, o); float y0 = e + o;
    unpack2(y1p, e, o); float y1 = e + o;
    unpack2(y2p, e, o); float y2 = e + o;

    // Reduce over the 4 sibling lanes (adjacent lanes: xor 1, then 2).
    #pragma unroll
    for (int d = 1; d < 4; d <<= 1) {
        y0 += __shfl_xor_sync(0xffffffffu, y0, d);
        y1 += __shfl_xor_sync(0xffffffffu, y1, d);
        y2 += __shfl_xor_sync(0xffffffffu, y2, d);
    }

    if (sub < F_OUT) {
        float v = (sub == 0) ? y0 : (sub == 1) ? y1 : y2;
        out[node * F_OUT + sub] = v + cAll[OFF_B2 + sub];
    }
}

extern "C" void kernel_launch(void* const* d_in, const int* in_sizes, int n_in,
                              void* d_out, int out_size) {
    const float* mailbox = (const float*)d_in[0];
    float* out = (float*)d_out;

    // 1) Pack weights into contiguous device staging (kernel node).
    gather_weights<<<1, 512>>>((const float*)d_in[1], (const float*)d_in[2],
                               (const float*)d_in[3], (const float*)d_in[4]);
    // 2) Single D2D copy into constant memory (graph-capturable).
    void* stage_ptr = nullptr;
    cudaGetSymbolAddress(&stage_ptr, g_stage);
    cudaMemcpyToSymbolAsync(cAll, stage_ptr, W_TOTAL * sizeof(float), 0,
                            cudaMemcpyDeviceToDevice, 0);

    const int n_nodes = in_sizes[0] / (KNBR * F_IN);
    const long long total_threads = (long long)n_nodes * 4;
    const int blocks = (int)((total_threads + BLOCK - 1) / BLOCK);

    aggre_mlp_kernel<<<blocks, BLOCK>>>(mailbox, out, n_nodes);
}

// round 15
// speedup vs baseline: 1.6465x; 1.0178x over previous
#include <cuda_runtime.h>

#define KNBR 16
#define F_IN 7
#define F_HID 40
#define F_OUT 3
#define HP (F_HID / 2)      // 20 hidden pairs
#define BLOCK 128

// Combined constant layout (all 16B-aligned blocks):
//   W1[0..279]  row-major f*40+h
//   b1[280..319]
//   W2P[320..439]  packed h-pair layout, pre-scaled by 1/K:
//     for p: 6 floats = (W2[2p][0],W2[2p+1][0], W2[2p][1],W2[2p+1][1], W2[2p][2],W2[2p+1][2])
//   b2[440..442]
#define OFF_W1 0
#define OFF_B1 280
#define OFF_W2P 320
#define OFF_B2 440
#define W_TOTAL 444

typedef unsigned long long u64;

__constant__ __align__(16) float cAll[W_TOTAL];

// ---- f32x2 packed helpers (sm_103a) ----
__device__ __forceinline__ u64 pack2(float lo, float hi) {
    u64 r;
    asm("mov.b64 %0, {%1, %2};" : "=l"(r) : "f"(lo), "f"(hi));
    return r;
}
__device__ __forceinline__ u64 fma2(u64 a, u64 b, u64 c) {
    u64 d;
    asm("fma.rn.f32x2 %0, %1, %2, %3;" : "=l"(d) : "l"(a), "l"(b), "l"(c));
    return d;
}
__device__ __forceinline__ u64 add2(u64 a, u64 b) {
    u64 d;
    asm("add.rn.f32x2 %0, %1, %2;" : "=l"(d) : "l"(a), "l"(b));
    return d;
}
__device__ __forceinline__ void unpack2(u64 v, float& lo, float& hi) {
    asm("mov.b64 {%0, %1}, %2;" : "=f"(lo), "=f"(hi) : "l"(v));
}
__device__ __forceinline__ u64 relu2(u64 v) {
    float lo, hi;
    unpack2(v, lo, hi);
    return pack2(fmaxf(lo, 0.f), fmaxf(hi, 0.f));   // FMNMX on alu pipe
}
__device__ __forceinline__ u64 f4lo(const float4& v) { return pack2(v.x, v.y); }
__device__ __forceinline__ u64 f4hi(const float4& v) { return pack2(v.z, v.w); }

// Pack all weights DIRECTLY into cAll's backing storage (single graph node).
// The constant cache is invalidated at launch boundaries, so the main kernel's
// LDC reads see these STG writes (same coherence path memcpyToSymbol relies on).
__global__ void gather_weights(float* __restrict__ cdst,
                               const float* __restrict__ W1,
                               const float* __restrict__ b1,
                               const float* __restrict__ W2,
                               const float* __restrict__ b2) {
    int i = threadIdx.x;
    if (i < 280)      cdst[OFF_W1 + i]       = W1[i];
    else if (i < 320) cdst[OFF_B1 + i - 280] = b1[i - 280];
    else if (i < 440) {
        int j = i - 320;                 // packed W2P index
        int p = j / 6, s = j % 6;        // pair p, slot s
        int o = s >> 1;                  // output index
        int h = 2 * p + (s & 1);         // which h of the pair
        cdst[OFF_W2P + j] = W2[h * F_OUT + o] * (1.0f / (float)KNBR);
    }
    else if (i < 443) cdst[OFF_B2 + i - 440] = b2[i - 440];
}

__global__ __launch_bounds__(BLOCK, 6)
void aggre_mlp_kernel(const float* __restrict__ mailbox,
                      float* __restrict__ out,
                      int n_nodes) {
    const int tid = threadIdx.x;
    const long long gt = (long long)blockIdx.x * BLOCK + tid;
    if (gt >= (long long)n_nodes * 4) return;

    const long long node = gt >> 2;          // 4 threads per node
    const int sub = (int)(gt & 3);

    // 4 messages * 7 floats = 7 float4, contiguous & 16B aligned.
    const float4* src = reinterpret_cast<const float4*>(mailbox) + node * 28 + sub * 7;
    // Duplicate each message scalar into both f32x2 halves (operand-a).
    u64 md[28];
    #pragma unroll
    for (int i = 0; i < 7; i++) {
        float4 v = src[i];
        md[4 * i + 0] = pack2(v.x, v.x);
        md[4 * i + 1] = pack2(v.y, v.y);
        md[4 * i + 2] = pack2(v.z, v.z);
        md[4 * i + 3] = pack2(v.w, v.w);
    }

    // Output accumulators, packed over (even h, odd h) of each pair.
    u64 y0p = pack2(0.f, 0.f);
    u64 y1p = pack2(0.f, 0.f);
    u64 y2p = pack2(0.f, 0.f);

    const float4* cW1q = reinterpret_cast<const float4*>(&cAll[OFF_W1]);  // stride 10 per f
    const float4* cB1q = reinterpret_cast<const float4*>(&cAll[OFF_B1]);
    const float4* cW2q = reinterpret_cast<const float4*>(&cAll[OFF_W2P]);

    // Process 2 h-pairs (4 hidden units) per iteration -> wide LDC.128 const
    // reads (11 per block vs 22 narrow), staying under the const-port floor.
    #pragma unroll
    for (int j = 0; j < HP / 2; j++) {       // j-th 4-h block: pairs 2j, 2j+1
        const float4 bq = cB1q[j];           // b1[4j..4j+3]
        const u64 bpA = f4lo(bq), bpB = f4hi(bq);
        u64 a0 = bpA, a1 = bpA, a2 = bpA, a3 = bpA;   // pair A chains
        u64 c0 = bpB, c1 = bpB, c2 = bpB, c3 = bpB;   // pair B chains
        #pragma unroll
        for (int f = 0; f < F_IN; f++) {
            const float4 wq = cW1q[f * 10 + j];       // W1[f][4j..4j+3]
            const u64 wA = f4lo(wq), wB = f4hi(wq);
            a0 = fma2(md[f],      wA, a0);  c0 = fma2(md[f],      wB, c0);
            a1 = fma2(md[7  + f], wA, a1);  c1 = fma2(md[7  + f], wB, c1);
            a2 = fma2(md[14 + f], wA, a2);  c2 = fma2(md[14 + f], wB, c2);
            a3 = fma2(md[21 + f], wA, a3);  c3 = fma2(md[21 + f], wB, c3);
        }
        // relu (alu pipe) + packed sum over 4 messages (3 add2 per pair)
        const u64 hsA = add2(add2(relu2(a0), relu2(a1)),
                             add2(relu2(a2), relu2(a3)));
        const u64 hsB = add2(add2(relu2(c0), relu2(c1)),
                             add2(relu2(c2), relu2(c3)));
        // layer 2 folded through mean; packed W2 pairs, 3 LDC.128 per block
        const float4 w2q0 = cW2q[3 * j + 0];  // (A.o0, A.o1)
        const float4 w2q1 = cW2q[3 * j + 1];  // (A.o2, B.o0)
        const float4 w2q2 = cW2q[3 * j + 2];  // (B.o1, B.o2)
        y0p = fma2(hsA, f4lo(w2q0), y0p);
        y1p = fma2(hsA, f4hi(w2q0), y1p);
        y2p = fma2(hsA, f4lo(w2q1), y2p);
        y0p = fma2(hsB, f4hi(w2q1), y0p);
        y1p = fma2(hsB, f4lo(w2q2), y1p);
        y2p = fma2(hsB, f4hi(w2q2), y2p);
    }

    float e, o;
    unpack2(y0p, e, o); float y0 = e + o;
    unpack2(y1p, e, o); float y1 = e + o;
    unpack2(y2p, e, o); float y2 = e + o;

    // Reduce over the 4 sibling lanes (adjacent lanes: xor 1, then 2).
    #pragma unroll
    for (int d = 1; d < 4; d <<= 1) {
        y0 += __shfl_xor_sync(0xffffffffu, y0, d);
        y1 += __shfl_xor_sync(0xffffffffu, y1, d);
        y2 += __shfl_xor_sync(0xffffffffu, y2, d);
    }

    if (sub < F_OUT) {
        float v = (sub == 0) ? y0 : (sub == 1) ? y1 : y2;
        out[node * F_OUT + sub] = v + cAll[OFF_B2 + sub];
    }
}

extern "C" void kernel_launch(void* const* d_in, const int* in_sizes, int n_in,
                              void* d_out, int out_size) {
    const float* mailbox = (const float*)d_in[0];
    float* out = (float*)d_out;

    // Single staging node: gather kernel writes straight into the constant
    // symbol's backing memory (no memcpy node).
    void* cAll_ptr = nullptr;
    cudaGetSymbolAddress(&cAll_ptr, cAll);
    gather_weights<<<1, 512>>>((float*)cAll_ptr,
                               (const float*)d_in[1], (const float*)d_in[2],
                               (const float*)d_in[3], (const float*)d_in[4]);

    const int n_nodes = in_sizes[0] / (KNBR * F_IN);
    const long long total_threads = (long long)n_nodes * 4;
    const int blocks = (int)((total_threads + BLOCK - 1) / BLOCK);

    aggre_mlp_kernel<<<blocks, BLOCK>>>(mailbox, out, n_nodes);
}